// round 3
// baseline (speedup 1.0000x reference)
#include <cuda_runtime.h>

#define NN 64
#define CC 960
#define CS 240
#define HW 784
#define HW4 196   // 784 / 4 float4s per (n,c) plane
#define NC (NN*CC)

// Scratch (no device allocs allowed): pooled means and final gate scales.
__device__ float g_pooled[NC];
__device__ float g_scale[NC];

// ---------------------------------------------------------------------------
// Kernel 1: global average pool. One warp per (n,c) plane (784 floats).
// ---------------------------------------------------------------------------
__global__ void pool_kernel(const float* __restrict__ x) {
    unsigned warp = (blockIdx.x * blockDim.x + threadIdx.x) >> 5;
    unsigned lane = threadIdx.x & 31u;
    if (warp >= NC) return;
    const float4* p = reinterpret_cast<const float4*>(x) + (size_t)warp * HW4;
    float s = 0.f;
    #pragma unroll 7
    for (int i = lane; i < HW4; i += 32) {
        float4 v = p[i];
        s += (v.x + v.y) + (v.z + v.w);
    }
    #pragma unroll
    for (int o = 16; o; o >>= 1) s += __shfl_xor_sync(0xffffffffu, s, o);
    if (lane == 0) g_pooled[warp] = s * (1.0f / HW);
}

// ---------------------------------------------------------------------------
// Kernel 2: tiny SE MLP. One block per batch row n.
//   h = relu(pooled @ w1^T + b1)   [240]
//   s = h @ w2^T + b2              [960]
//   scale = hardsigmoid(s) = saturate((s+3)/6)
// Warp-per-output, lane-parallel (coalesced) reduction over k.
// ---------------------------------------------------------------------------
__global__ void se_fc_kernel(const float* __restrict__ w1, const float* __restrict__ b1,
                             const float* __restrict__ w2, const float* __restrict__ b2) {
    __shared__ float pr[CC];
    __shared__ float hh[CS];
    const int n    = blockIdx.x;
    const int tid  = threadIdx.x;
    const int warp = tid >> 5;
    const int lane = tid & 31;

    for (int i = tid; i < CC; i += blockDim.x) pr[i] = g_pooled[n * CC + i];
    __syncthreads();

    // fc1 + relu: 240 outputs across 8 warps
    for (int o = warp; o < CS; o += 8) {
        float s = 0.f;
        const float* wr = w1 + o * CC;
        for (int k = lane; k < CC; k += 32) s += wr[k] * pr[k];
        #pragma unroll
        for (int d = 16; d; d >>= 1) s += __shfl_xor_sync(0xffffffffu, s, d);
        if (lane == 0) hh[o] = fmaxf(s + b1[o], 0.f);
    }
    __syncthreads();

    // fc2 + hardsigmoid: 960 outputs across 8 warps
    for (int c = warp; c < CC; c += 8) {
        float s = 0.f;
        const float* wr = w2 + c * CS;
        for (int k = lane; k < CS; k += 32) s += wr[k] * hh[k];
        #pragma unroll
        for (int d = 16; d; d >>= 1) s += __shfl_xor_sync(0xffffffffu, s, d);
        if (lane == 0) {
            float v = (s + b2[c] + 3.f) * (1.f / 6.f);
            g_scale[n * CC + c] = __saturatef(v);
        }
    }
}

// ---------------------------------------------------------------------------
// Kernel 3: out = scale[n,c] * x. Pure streaming float4 multiply.
// total float4s = 12,042,240; one per thread, exact grid.
// ---------------------------------------------------------------------------
__global__ void scale_kernel(const float* __restrict__ x, float* __restrict__ out) {
    unsigned i = blockIdx.x * blockDim.x + threadIdx.x;   // < 12,042,240 (fits u32)
    unsigned nc = i / HW4;                                // (n,c) plane index
    float sc = __ldg(&g_scale[nc]);
    float4 v = reinterpret_cast<const float4*>(x)[i];
    v.x *= sc; v.y *= sc; v.z *= sc; v.w *= sc;
    reinterpret_cast<float4*>(out)[i] = v;
}

// ---------------------------------------------------------------------------
extern "C" void kernel_launch(void* const* d_in, const int* in_sizes, int n_in,
                              void* d_out, int out_size) {
    const float* x  = (const float*)d_in[0];
    const float* w1 = (const float*)d_in[1];
    const float* b1 = (const float*)d_in[2];
    const float* w2 = (const float*)d_in[3];
    const float* b2 = (const float*)d_in[4];
    float* out = (float*)d_out;

    // 61440 warps -> 7680 blocks of 256 threads
    pool_kernel<<<(NC * 32) / 256, 256>>>(x);
    se_fc_kernel<<<NN, 256>>>(w1, b1, w2, b2);
    // 12,042,240 float4s / 256 = 47040 blocks exactly
    scale_kernel<<<47040, 256>>>(x, out);
}

// round 5
// speedup vs baseline: 1.8378x; 1.8378x over previous
#include <cuda_runtime.h>

#define NN 64
#define CC 960
#define CS 240
#define HW 784
#define HW4 196   // 784 / 4 float4s per (n,c) plane
#define NC (NN*CC)

// Scratch (no device allocs allowed).
__device__ float g_pooled[NC];
__device__ float g_hidden[NN*CS];
__device__ float g_scale[NC];

// ---------------------------------------------------------------------------
// Kernel 1: global average pool. One warp per (n,c) plane (784 floats).
// ---------------------------------------------------------------------------
__global__ void pool_kernel(const float* __restrict__ x) {
    unsigned warp = (blockIdx.x * blockDim.x + threadIdx.x) >> 5;
    unsigned lane = threadIdx.x & 31u;
    if (warp >= NC) return;
    const float4* p = reinterpret_cast<const float4*>(x) + (size_t)warp * HW4;
    float s = 0.f;
    #pragma unroll 7
    for (int i = lane; i < HW4; i += 32) {
        float4 v = p[i];
        s += (v.x + v.y) + (v.z + v.w);
    }
    #pragma unroll
    for (int o = 16; o; o >>= 1) s += __shfl_xor_sync(0xffffffffu, s, o);
    if (lane == 0) g_pooled[warp] = s * (1.0f / HW);
}

// ---------------------------------------------------------------------------
// Kernel 2a: fc1 + relu. One warp per (n, o) output; 64*240 = 15360 warps.
//   h[n,o] = relu(dot(pooled[n,:], w1[o,:]) + b1[o])   (dot over 960)
// ---------------------------------------------------------------------------
__global__ void fc1_kernel(const float* __restrict__ w1, const float* __restrict__ b1) {
    unsigned w    = (blockIdx.x * blockDim.x + threadIdx.x) >> 5;   // < 15360
    unsigned lane = threadIdx.x & 31u;
    unsigned n = w / CS;
    unsigned o = w % CS;
    const float4* wr = reinterpret_cast<const float4*>(w1) + (size_t)o * (CC / 4);
    const float4* pr = reinterpret_cast<const float4*>(g_pooled) + (size_t)n * (CC / 4);
    float s = 0.f;
    #pragma unroll 8
    for (int i = lane; i < CC / 4; i += 32) {               // 240 float4s
        float4 a = wr[i], b = pr[i];
        s += a.x * b.x + a.y * b.y + a.z * b.z + a.w * b.w;
    }
    #pragma unroll
    for (int d = 16; d; d >>= 1) s += __shfl_xor_sync(0xffffffffu, s, d);
    if (lane == 0) g_hidden[n * CS + o] = fmaxf(s + b1[o], 0.f);
}

// ---------------------------------------------------------------------------
// Kernel 2b: fc2 + hardsigmoid. One warp per (n, c); 64*960 = 61440 warps.
//   scale[n,c] = saturate((dot(h[n,:], w2[c,:]) + b2[c] + 3) / 6)   (dot over 240)
// ---------------------------------------------------------------------------
__global__ void fc2_kernel(const float* __restrict__ w2, const float* __restrict__ b2) {
    unsigned w    = (blockIdx.x * blockDim.x + threadIdx.x) >> 5;   // < 61440
    unsigned lane = threadIdx.x & 31u;
    unsigned n = w / CC;
    unsigned c = w % CC;
    const float4* wr = reinterpret_cast<const float4*>(w2) + (size_t)c * (CS / 4);
    const float4* hr = reinterpret_cast<const float4*>(g_hidden) + (size_t)n * (CS / 4);
    float s = 0.f;
    #pragma unroll 2
    for (int i = lane; i < CS / 4; i += 32) {               // 60 float4s
        float4 a = wr[i], b = hr[i];
        s += a.x * b.x + a.y * b.y + a.z * b.z + a.w * b.w;
    }
    #pragma unroll
    for (int d = 16; d; d >>= 1) s += __shfl_xor_sync(0xffffffffu, s, d);
    if (lane == 0) {
        float v = (s + b2[c] + 3.f) * (1.f / 6.f);
        g_scale[n * CC + c] = __saturatef(v);
    }
}

// ---------------------------------------------------------------------------
// Kernel 3: out = scale[n,c] * x. Pure streaming float4 multiply.
// Streaming hints: x is never read again (evict-first), out is write-once.
// ---------------------------------------------------------------------------
__global__ void scale_kernel(const float* __restrict__ x, float* __restrict__ out) {
    unsigned i  = blockIdx.x * blockDim.x + threadIdx.x;    // < 12,042,240
    unsigned nc = i / HW4;
    float sc = __ldg(&g_scale[nc]);
    float4 v = __ldcs(reinterpret_cast<const float4*>(x) + i);
    v.x *= sc; v.y *= sc; v.z *= sc; v.w *= sc;
    __stcs(reinterpret_cast<float4*>(out) + i, v);
}

// ---------------------------------------------------------------------------
extern "C" void kernel_launch(void* const* d_in, const int* in_sizes, int n_in,
                              void* d_out, int out_size) {
    const float* x  = (const float*)d_in[0];
    const float* w1 = (const float*)d_in[1];
    const float* b1 = (const float*)d_in[2];
    const float* w2 = (const float*)d_in[3];
    const float* b2 = (const float*)d_in[4];
    float* out = (float*)d_out;

    pool_kernel<<<(NC * 32) / 256, 256>>>(x);               // 7680 blocks
    fc1_kernel<<<(NN * CS * 32) / 256, 256>>>(w1, b1);      // 1920 blocks
    fc2_kernel<<<(NN * CC * 32) / 256, 256>>>(w2, b2);      // 7680 blocks
    scale_kernel<<<47040, 256>>>(x, out);                   // exact grid
}